// round 2
// baseline (speedup 1.0000x reference)
#include <cuda_runtime.h>

#define N_NODES 100000
#define D_HID   512
#define E_MAX   800000

static __device__ __align__(16) float g_dinv[N_NODES];
static __device__ __align__(16) float g_buf_h[(size_t)N_NODES * D_HID];
static __device__ __align__(16) float g_buf_a[(size_t)N_NODES * D_HID];
static __device__ int g_row[E_MAX];
static __device__ int g_col[E_MAX];
static __device__ int g_is32;

// ---------------------------------------------------------------- dtype handling
__global__ void k_zero_flag() { g_is32 = 0; }

// Interpret buffer as int64; any out-of-range value => data is really int32.
__global__ void k_detect(const long long* __restrict__ p, int n) {
    int i = blockIdx.x * blockDim.x + threadIdx.x;
    if (i < n) {
        long long v = p[i];
        if (v < 0 || v >= N_NODES) atomicOr(&g_is32, 1);
    }
}

__global__ void k_convert(const void* __restrict__ ei, int E,
                          int* __restrict__ row, int* __restrict__ col) {
    int i = blockIdx.x * blockDim.x + threadIdx.x;
    if (i >= E) return;
    if (g_is32) {
        const int* p = (const int*)ei;
        row[i] = p[i];
        col[i] = p[E + i];
    } else {
        const long long* p = (const long long*)ei;
        row[i] = (int)p[i];
        col[i] = (int)p[E + i];
    }
}

// ---------------------------------------------------------------- utilities
__global__ void k_fill(float* __restrict__ p, float v, int n) {
    int i = blockIdx.x * blockDim.x + threadIdx.x;
    if (i < n) p[i] = v;
}

__global__ void k_count(const int* __restrict__ rows, float* __restrict__ deg, int E) {
    int i = blockIdx.x * blockDim.x + threadIdx.x;
    if (i < E) atomicAdd(&deg[rows[i]], 1.0f);
}

__global__ void k_rsqrt(float* __restrict__ p, int n) {
    int i = blockIdx.x * blockDim.x + threadIdx.x;
    if (i < n) p[i] = rsqrtf(p[i]);
}

// a[i,:] = dinv[i]^2 * h[i,:] + bias[:]   (self-loop term + bias, float4)
__global__ void k_agg_init(const float4* __restrict__ h, const float* __restrict__ dinv,
                           const float4* __restrict__ bias, float4* __restrict__ a, int total4) {
    int i = blockIdx.x * blockDim.x + threadIdx.x;
    if (i >= total4) return;
    int row = i >> 7;          // 512/4 = 128 float4 per row
    int j   = i & 127;
    float w = dinv[row];
    w = w * w;
    float4 v = h[i];
    float4 b = bias[j];
    v.x = fmaf(w, v.x, b.x);
    v.y = fmaf(w, v.y, b.y);
    v.z = fmaf(w, v.z, b.z);
    v.w = fmaf(w, v.w, b.w);
    a[i] = v;
}

__device__ __forceinline__ void red_add_v4(float* addr, float4 v) {
    asm volatile("red.global.add.v4.f32 [%0], {%1, %2, %3, %4};"
                 :: "l"(addr), "f"(v.x), "f"(v.y), "f"(v.z), "f"(v.w)
                 : "memory");
}

// one warp per edge: a[row,:] += dinv[row]*dinv[col] * h[col,:]
__global__ void k_agg_edges(const int* __restrict__ rows,
                            const int* __restrict__ cols,
                            const float* __restrict__ dinv,
                            const float* __restrict__ h,
                            float* __restrict__ a, int E) {
    int gw   = (int)((blockIdx.x * blockDim.x + threadIdx.x) >> 5);
    int lane = threadIdx.x & 31;
    if (gw >= E) return;
    int r = rows[gw];
    int c = cols[gw];
    float w = dinv[r] * dinv[c];
    const float4* hs = (const float4*)(h + (size_t)c * D_HID);
    float*        ad = a + (size_t)r * D_HID;
#pragma unroll
    for (int i = 0; i < 4; i++) {
        float4 v = hs[lane + i * 32];
        v.x *= w; v.y *= w; v.z *= w; v.w *= w;
        red_add_v4(ad + (size_t)(lane + i * 32) * 4, v);
    }
}

// ---------------------------------------------------------------- SGEMM
// C[N,M] = op(A)[N,K] @ B[K,M] (+ bias)   op = optional ReLU on A-load
// BM=128, BN=128, BK=8, 256 threads, TM=TN=8
__global__ __launch_bounds__(256)
void k_gemm(const float* __restrict__ A, const float* __restrict__ B,
            float* __restrict__ C, int N, int K, int M,
            const float* __restrict__ bias, int reluA) {
    const int BM = 128, BN = 128, BK = 8, TM = 8, TN = 8;
    __shared__ float As[BK][BM];
    __shared__ float Bs[BK][BN];

    int tid  = threadIdx.x;
    int brow = blockIdx.x * BM;
    int bcol = blockIdx.y * BN;

    int arow = tid >> 1;
    int acol = (tid & 1) << 2;
    int browB = tid >> 5;
    int bcolB = (tid & 31) << 2;

    int ty = tid >> 4, tx = tid & 15;

    float acc[TM][TN];
#pragma unroll
    for (int i = 0; i < TM; i++)
#pragma unroll
        for (int j = 0; j < TN; j++) acc[i][j] = 0.f;

    int grow = brow + arow;
    bool av_ok = grow < N;
    const float* Ap = A + (size_t)grow * K + acol;
    const float* Bp = B + (size_t)browB * M + bcol + bcolB;

    for (int k0 = 0; k0 < K; k0 += BK) {
        float4 av = av_ok ? __ldg((const float4*)(Ap + k0))
                          : make_float4(0.f, 0.f, 0.f, 0.f);
        if (reluA) {
            av.x = fmaxf(av.x, 0.f); av.y = fmaxf(av.y, 0.f);
            av.z = fmaxf(av.z, 0.f); av.w = fmaxf(av.w, 0.f);
        }
        As[acol + 0][arow] = av.x;
        As[acol + 1][arow] = av.y;
        As[acol + 2][arow] = av.z;
        As[acol + 3][arow] = av.w;
        *(float4*)&Bs[browB][bcolB] = __ldg((const float4*)(Bp + (size_t)k0 * M));
        __syncthreads();

#pragma unroll
        for (int k = 0; k < BK; k++) {
            float ar[TM], br[TN];
#pragma unroll
            for (int i = 0; i < TM; i++) ar[i] = As[k][ty * TM + i];
#pragma unroll
            for (int j = 0; j < TN; j++) br[j] = Bs[k][tx * TN + j];
#pragma unroll
            for (int i = 0; i < TM; i++)
#pragma unroll
                for (int j = 0; j < TN; j++)
                    acc[i][j] = fmaf(ar[i], br[j], acc[i][j]);
        }
        __syncthreads();
    }

#pragma unroll
    for (int i = 0; i < TM; i++) {
        int row = brow + ty * TM + i;
        if (row >= N) continue;
#pragma unroll
        for (int j = 0; j < TN; j += 4) {
            int col = bcol + tx * TN + j;
            float4 v = make_float4(acc[i][j], acc[i][j + 1], acc[i][j + 2], acc[i][j + 3]);
            if (bias) {
                v.x += bias[col];     v.y += bias[col + 1];
                v.z += bias[col + 2]; v.w += bias[col + 3];
            }
            *(float4*)(C + (size_t)row * M + col) = v;
        }
    }
}

// ---------------------------------------------------------------- launch
extern "C" void kernel_launch(void* const* d_in, const int* in_sizes, int n_in,
                              void* d_out, int out_size) {
    const float* x   = (const float*)d_in[0];
    const void*  ei  = d_in[1];
    const float* W1  = (const float*)d_in[2];
    const float* b1  = (const float*)d_in[3];
    const float* W2  = (const float*)d_in[4];
    const float* b2  = (const float*)d_in[5];
    const float* W3  = (const float*)d_in[6];
    const float* b3  = (const float*)d_in[7];
    const float* Wfc = (const float*)d_in[8];
    const float* bfc = (const float*)d_in[9];
    int E = in_sizes[1] / 2;
    if (E > E_MAX) E = E_MAX;

    float *dinv, *h, *a;
    int *row, *col;
    cudaGetSymbolAddress((void**)&dinv, g_dinv);
    cudaGetSymbolAddress((void**)&h,    g_buf_h);
    cudaGetSymbolAddress((void**)&a,    g_buf_a);
    cudaGetSymbolAddress((void**)&row,  g_row);
    cudaGetSymbolAddress((void**)&col,  g_col);

    const int T = 256;
    int gE = (E + T - 1) / T;

    // ---- edge index dtype detection + conversion to int32 scratch
    k_zero_flag<<<1, 1>>>();
    k_detect <<<gE, T>>>((const long long*)ei, E);
    k_convert<<<gE, T>>>(ei, E, row, col);

    // ---- degree (with self-loop) -> dinv
    k_fill <<<(N_NODES + T - 1) / T, T>>>(dinv, 1.0f, N_NODES);
    k_count<<<gE, T>>>(row, dinv, E);
    k_rsqrt<<<(N_NODES + T - 1) / T, T>>>(dinv, N_NODES);

    dim3 gridH((N_NODES + 127) / 128, 4);
    dim3 gridO((N_NODES + 127) / 128, 2);
    int total4 = N_NODES * (D_HID / 4);
    int gInit  = (total4 + T - 1) / T;
    int gEdge  = (int)(((long long)E * 32 + T - 1) / T);

    // layer 1
    k_gemm<<<gridH, 256>>>(x, W1, h, N_NODES, 256, 512, nullptr, 0);
    k_agg_init <<<gInit, T>>>((const float4*)h, dinv, (const float4*)b1, (float4*)a, total4);
    k_agg_edges<<<gEdge, T>>>(row, col, dinv, h, a, E);

    // layer 2
    k_gemm<<<gridH, 256>>>(a, W2, h, N_NODES, 512, 512, nullptr, 1);
    k_agg_init <<<gInit, T>>>((const float4*)h, dinv, (const float4*)b2, (float4*)a, total4);
    k_agg_edges<<<gEdge, T>>>(row, col, dinv, h, a, E);

    // layer 3
    k_gemm<<<gridH, 256>>>(a, W3, h, N_NODES, 512, 512, nullptr, 1);
    k_agg_init <<<gInit, T>>>((const float4*)h, dinv, (const float4*)b3, (float4*)a, total4);
    k_agg_edges<<<gEdge, T>>>(row, col, dinv, h, a, E);

    // final FC
    k_gemm<<<gridO, 256>>>(a, Wfc, (float*)d_out, N_NODES, 512, 256, bfc, 1);
}

// round 4
// speedup vs baseline: 1.4590x; 1.4590x over previous
#include <cuda_runtime.h>
#include <cuda_bf16.h>
#include <cstdint>

#define N_NODES 100000
#define N_PAD   100096          // 782 * 128
#define D_HID   512
#define E_MAX   800000

static __device__ __align__(16)  float g_dinv[N_NODES];
static __device__ __align__(256) float g_buf_h[(size_t)N_NODES * D_HID];
static __device__ __align__(256) float g_buf_a[(size_t)N_NODES * D_HID];
static __device__ __align__(256) __nv_bfloat16 g_ahi[(size_t)N_PAD * D_HID];
static __device__ __align__(256) __nv_bfloat16 g_alo[(size_t)N_PAD * D_HID];
static __device__ __align__(256) __nv_bfloat16 g_whi[512 * 512];
static __device__ __align__(256) __nv_bfloat16 g_wlo[512 * 512];
static __device__ int g_row[E_MAX];
static __device__ int g_col[E_MAX];
static __device__ int g_is32;

// ================================================================ helpers
__device__ __forceinline__ uint32_t smem_u32(const void* p) {
    uint32_t a;
    asm("{ .reg .u64 t; cvta.to.shared.u64 t, %1; cvt.u32.u64 %0, t; }" : "=r"(a) : "l"(p));
    return a;
}
__device__ __forceinline__ void cp16(uint32_t dst, const void* src) {
    asm volatile("cp.async.cg.shared.global [%0], [%1], 16;" :: "r"(dst), "l"(src) : "memory");
}
__device__ __forceinline__ void ldx4(uint32_t r[4], uint32_t addr) {
    asm volatile("ldmatrix.sync.aligned.m8n8.x4.shared.b16 {%0,%1,%2,%3}, [%4];"
                 : "=r"(r[0]), "=r"(r[1]), "=r"(r[2]), "=r"(r[3]) : "r"(addr));
}
__device__ __forceinline__ void mma_bf16(float c[4], const uint32_t a[4], uint32_t b0, uint32_t b1) {
    asm volatile("mma.sync.aligned.m16n8k16.row.col.f32.bf16.bf16.f32 "
                 "{%0,%1,%2,%3}, {%4,%5,%6,%7}, {%8,%9}, {%0,%1,%2,%3};"
                 : "+f"(c[0]), "+f"(c[1]), "+f"(c[2]), "+f"(c[3])
                 : "r"(a[0]), "r"(a[1]), "r"(a[2]), "r"(a[3]), "r"(b0), "r"(b1));
}

// ================================================================ bf16 MMA GEMM
// C[nrows, Nout](fp32) = Ahi/Alo[N_PAD, K](bf16) @ (Whi/Wlo[Nout, K])^T  (+bias)
// grid (nrows/128, Nout/128), 256 thr. BK=32, 2-stage cp.async pipeline.
// smem: per stage [Ahi|Alo|Whi|Wlo], each 128 rows x stride-40 bf16 (80B rows).
__global__ __launch_bounds__(256, 1)
void k_gemm_mma(const __nv_bfloat16* __restrict__ Ahi, const __nv_bfloat16* __restrict__ Alo,
                int K,
                const __nv_bfloat16* __restrict__ Whi, const __nv_bfloat16* __restrict__ Wlo,
                float* __restrict__ C, int Nout, const float* __restrict__ bias, int nrows) {
    extern __shared__ char smem[];
    const uint32_t sb = smem_u32(smem);
    const int MTX = 10240;           // 128 * 80 bytes
    const int STAGE = 4 * MTX;       // 40 KB

    const int tid = threadIdx.x, wid = tid >> 5, lane = tid & 31;
    const int wm = wid & 3, wn = wid >> 2;
    const int brow = blockIdx.x * 128, bcol = blockIdx.y * 128;
    const int nit = K >> 5;

    // cp.async mapping: 2 x 16B chunks per thread per matrix
    const int c0 = tid * 2, c1 = tid * 2 + 1;
    const int r0 = c0 >> 2, k16_0 = c0 & 3;
    const int r1 = c1 >> 2, k16_1 = c1 & 3;

    // ldmatrix address components
    const int g = lane >> 3, lr = lane & 7;
    const uint32_t a_row = (uint32_t)(wm * 32 + (g & 1) * 8 + lr);
    const uint32_t b_row = (uint32_t)(wn * 64 + (g & 1) * 8 + lr);
    const uint32_t kg = (uint32_t)((g >> 1) * 16);   // byte offset within k-chunk

    float acc[2][8][4];
#pragma unroll
    for (int m = 0; m < 2; m++)
#pragma unroll
        for (int n = 0; n < 8; n++)
#pragma unroll
            for (int v = 0; v < 4; v++) acc[m][n][v] = 0.f;

#define LOAD_STAGE(I) do {                                                            \
    int _st = (I) & 1; uint32_t _d = sb + _st * STAGE; int _k0 = (I) * 32;            \
    cp16(_d + r0 * 80 + k16_0 * 16,           Ahi + (size_t)(brow + r0) * K + _k0 + k16_0 * 8); \
    cp16(_d + r1 * 80 + k16_1 * 16,           Ahi + (size_t)(brow + r1) * K + _k0 + k16_1 * 8); \
    cp16(_d + MTX + r0 * 80 + k16_0 * 16,     Alo + (size_t)(brow + r0) * K + _k0 + k16_0 * 8); \
    cp16(_d + MTX + r1 * 80 + k16_1 * 16,     Alo + (size_t)(brow + r1) * K + _k0 + k16_1 * 8); \
    cp16(_d + 2 * MTX + r0 * 80 + k16_0 * 16, Whi + (size_t)(bcol + r0) * K + _k0 + k16_0 * 8); \
    cp16(_d + 2 * MTX + r1 * 80 + k16_1 * 16, Whi + (size_t)(bcol + r1) * K + _k0 + k16_1 * 8); \
    cp16(_d + 3 * MTX + r0 * 80 + k16_0 * 16, Wlo + (size_t)(bcol + r0) * K + _k0 + k16_0 * 8); \
    cp16(_d + 3 * MTX + r1 * 80 + k16_1 * 16, Wlo + (size_t)(bcol + r1) * K + _k0 + k16_1 * 8); \
    asm volatile("cp.async.commit_group;" ::: "memory");                              \
} while (0)

    LOAD_STAGE(0);

    for (int i = 0; i < nit; i++) {
        if (i + 1 < nit) {
            LOAD_STAGE(i + 1);
            asm volatile("cp.async.wait_group 1;" ::: "memory");
        } else {
            asm volatile("cp.async.wait_group 0;" ::: "memory");
        }
        __syncthreads();

        const uint32_t base = sb + (i & 1) * STAGE;
#pragma unroll
        for (int kst = 0; kst < 2; kst++) {
            const uint32_t acol = kg + kst * 32;
            uint32_t ah[2][4], al[2][4], bh[4][4], bl[4][4];
#pragma unroll
            for (int m = 0; m < 2; m++) {
                uint32_t aa = base + (a_row + m * 16) * 80 + acol;
                ldx4(ah[m], aa);
                ldx4(al[m], aa + MTX);
            }
#pragma unroll
            for (int p = 0; p < 4; p++) {
                uint32_t ba = base + 2 * MTX + (b_row + p * 16) * 80 + acol;
                ldx4(bh[p], ba);
                ldx4(bl[p], ba + MTX);
            }
#pragma unroll
            for (int m = 0; m < 2; m++)
#pragma unroll
                for (int p = 0; p < 4; p++)
#pragma unroll
                    for (int s = 0; s < 2; s++) {
                        float* cc = acc[m][p * 2 + s];
                        mma_bf16(cc, ah[m], bh[p][s], bh[p][s + 2]);
                        mma_bf16(cc, ah[m], bl[p][s], bl[p][s + 2]);
                        mma_bf16(cc, al[m], bh[p][s], bh[p][s + 2]);
                    }
        }
        __syncthreads();
    }
#undef LOAD_STAGE

    // epilogue
    const int q = lane >> 2, qt = lane & 3;
#pragma unroll
    for (int m = 0; m < 2; m++) {
        int row = brow + wm * 32 + m * 16 + q;
#pragma unroll
        for (int n = 0; n < 8; n++) {
            int colb = bcol + wn * 64 + n * 8 + qt * 2;
            float* cc = acc[m][n];
            float bx = 0.f, by = 0.f;
            if (bias) { bx = bias[colb]; by = bias[colb + 1]; }
            if (row < nrows)
                *(float2*)(C + (size_t)row * Nout + colb) = make_float2(cc[0] + bx, cc[1] + by);
            if (row + 8 < nrows)
                *(float2*)(C + (size_t)(row + 8) * Nout + colb) = make_float2(cc[2] + bx, cc[3] + by);
        }
    }
}

// ================================================================ fp32 -> bf16 hi/lo split
__global__ void k_split(const float4* __restrict__ A, int relu,
                        __nv_bfloat16* __restrict__ hi, __nv_bfloat16* __restrict__ lo, int total4) {
    int i = blockIdx.x * blockDim.x + threadIdx.x;
    if (i >= total4) return;
    float4 v = A[i];
    if (relu) {
        v.x = fmaxf(v.x, 0.f); v.y = fmaxf(v.y, 0.f);
        v.z = fmaxf(v.z, 0.f); v.w = fmaxf(v.w, 0.f);
    }
    uint32_t ux = __float_as_uint(v.x), uy = __float_as_uint(v.y);
    uint32_t uz = __float_as_uint(v.z), uw = __float_as_uint(v.w);
    uint32_t hp0 = __byte_perm(ux, uy, 0x7632);
    uint32_t hp1 = __byte_perm(uz, uw, 0x7632);
    float rx = v.x - __uint_as_float(ux & 0xFFFF0000u);
    float ry = v.y - __uint_as_float(uy & 0xFFFF0000u);
    float rz = v.z - __uint_as_float(uz & 0xFFFF0000u);
    float rw = v.w - __uint_as_float(uw & 0xFFFF0000u);
    __nv_bfloat162 l01 = __floats2bfloat162_rn(rx, ry);
    __nv_bfloat162 l23 = __floats2bfloat162_rn(rz, rw);
    *(uint2*)(hi + (size_t)i * 4) = make_uint2(hp0, hp1);
    *(uint2*)(lo + (size_t)i * 4) = make_uint2(*(uint32_t*)&l01, *(uint32_t*)&l23);
}

// W fp32 [K][Nout] -> hi/lo bf16 [Nout][K] (transpose + split)
__global__ void k_wconv(const float* __restrict__ W, int K, int Nout,
                        __nv_bfloat16* __restrict__ whi, __nv_bfloat16* __restrict__ wlo) {
    int idx = blockIdx.x * blockDim.x + threadIdx.x;
    if (idx >= K * Nout) return;
    int k = idx / Nout, n = idx - k * Nout;
    float v = W[idx];
    uint32_t u = __float_as_uint(v);
    float h = __uint_as_float(u & 0xFFFF0000u);
    ushort hs = (ushort)(u >> 16);
    whi[(size_t)n * K + k] = *reinterpret_cast<__nv_bfloat16*>(&hs);
    wlo[(size_t)n * K + k] = __float2bfloat16_rn(v - h);
}

// ================================================================ edge prep
__global__ void k_zero_flag() { g_is32 = 0; }
__global__ void k_detect(const long long* __restrict__ p, int n) {
    int i = blockIdx.x * blockDim.x + threadIdx.x;
    if (i < n) {
        long long v = p[i];
        if (v < 0 || v >= N_NODES) atomicOr(&g_is32, 1);
    }
}
__global__ void k_convert(const void* __restrict__ ei, int E,
                          int* __restrict__ row, int* __restrict__ col) {
    int i = blockIdx.x * blockDim.x + threadIdx.x;
    if (i >= E) return;
    if (g_is32) {
        const int* p = (const int*)ei;
        row[i] = p[i]; col[i] = p[E + i];
    } else {
        const long long* p = (const long long*)ei;
        row[i] = (int)p[i]; col[i] = (int)p[E + i];
    }
}
__global__ void k_fill(float* __restrict__ p, float v, int n) {
    int i = blockIdx.x * blockDim.x + threadIdx.x;
    if (i < n) p[i] = v;
}
__global__ void k_count(const int* __restrict__ rows, float* __restrict__ deg, int E) {
    int i = blockIdx.x * blockDim.x + threadIdx.x;
    if (i < E) atomicAdd(&deg[rows[i]], 1.0f);
}
__global__ void k_rsqrt(float* __restrict__ p, int n) {
    int i = blockIdx.x * blockDim.x + threadIdx.x;
    if (i < n) p[i] = rsqrtf(p[i]);
}

// ================================================================ aggregation
__global__ void k_agg_init(const float4* __restrict__ h, const float* __restrict__ dinv,
                           const float4* __restrict__ bias, float4* __restrict__ a, int total4) {
    int i = blockIdx.x * blockDim.x + threadIdx.x;
    if (i >= total4) return;
    int row = i >> 7;
    int j = i & 127;
    float w = dinv[row]; w = w * w;
    float4 v = h[i];
    float4 b = bias[j];
    v.x = fmaf(w, v.x, b.x); v.y = fmaf(w, v.y, b.y);
    v.z = fmaf(w, v.z, b.z); v.w = fmaf(w, v.w, b.w);
    a[i] = v;
}

__device__ __forceinline__ void red_add_v4(float* addr, float4 v) {
    asm volatile("red.global.add.v4.f32 [%0], {%1, %2, %3, %4};"
                 :: "l"(addr), "f"(v.x), "f"(v.y), "f"(v.z), "f"(v.w) : "memory");
}

__global__ void k_agg_edges(const int* __restrict__ rows, const int* __restrict__ cols,
                            const float* __restrict__ dinv, const float* __restrict__ h,
                            float* __restrict__ a, int E) {
    int gw = (int)((blockIdx.x * blockDim.x + threadIdx.x) >> 5);
    int lane = threadIdx.x & 31;
    if (gw >= E) return;
    int r = rows[gw], c = cols[gw];
    float w = dinv[r] * dinv[c];
    const float4* hs = (const float4*)(h + (size_t)c * D_HID);
    float* ad = a + (size_t)r * D_HID;
#pragma unroll
    for (int i = 0; i < 4; i++) {
        float4 v = hs[lane + i * 32];
        v.x *= w; v.y *= w; v.z *= w; v.w *= w;
        red_add_v4(ad + (size_t)(lane + i * 32) * 4, v);
    }
}

// ================================================================ launch
extern "C" void kernel_launch(void* const* d_in, const int* in_sizes, int n_in,
                              void* d_out, int out_size) {
    const float* x   = (const float*)d_in[0];
    const void*  ei  = d_in[1];
    const float* W1  = (const float*)d_in[2];
    const float* b1  = (const float*)d_in[3];
    const float* W2  = (const float*)d_in[4];
    const float* b2  = (const float*)d_in[5];
    const float* W3  = (const float*)d_in[6];
    const float* b3  = (const float*)d_in[7];
    const float* Wfc = (const float*)d_in[8];
    const float* bfc = (const float*)d_in[9];
    int E = in_sizes[1] / 2;
    if (E > E_MAX) E = E_MAX;

    float *dinv, *h, *a;
    int *row, *col;
    __nv_bfloat16 *ahi, *alo, *whi, *wlo;
    cudaGetSymbolAddress((void**)&dinv, g_dinv);
    cudaGetSymbolAddress((void**)&h,    g_buf_h);
    cudaGetSymbolAddress((void**)&a,    g_buf_a);
    cudaGetSymbolAddress((void**)&row,  g_row);
    cudaGetSymbolAddress((void**)&col,  g_col);
    cudaGetSymbolAddress((void**)&ahi,  g_ahi);
    cudaGetSymbolAddress((void**)&alo,  g_alo);
    cudaGetSymbolAddress((void**)&whi,  g_whi);
    cudaGetSymbolAddress((void**)&wlo,  g_wlo);

    const int SMEM_GEMM = 2 * 4 * 10240;  // 80 KB
    cudaFuncSetAttribute(k_gemm_mma, cudaFuncAttributeMaxDynamicSharedMemorySize, SMEM_GEMM);

    const int T = 256;
    int gE = (E + T - 1) / T;

    // edge index dtype detect + int32 scratch
    k_zero_flag<<<1, 1>>>();
    k_detect <<<gE, T>>>((const long long*)ei, E);
    k_convert<<<gE, T>>>(ei, E, row, col);

    // degree (with self-loop) -> dinv
    k_fill <<<(N_NODES + T - 1) / T, T>>>(dinv, 1.0f, N_NODES);
    k_count<<<gE, T>>>(row, dinv, E);
    k_rsqrt<<<(N_NODES + T - 1) / T, T>>>(dinv, N_NODES);

    dim3 gridH((N_NODES + 127) / 128, 4);
    dim3 gridO((N_NODES + 127) / 128, 2);
    int total4 = N_NODES * (D_HID / 4);
    int gInit = (total4 + T - 1) / T;
    int gEdge = (int)(((long long)E * 32 + T - 1) / T);
    int s1 = N_NODES * 256 / 4, sH = N_NODES * 512 / 4;

    // layer 1: K=256
    k_split<<<(s1 + T - 1) / T, T>>>((const float4*)x, 0, ahi, alo, s1);
    k_wconv<<<(256 * 512 + T - 1) / T, T>>>(W1, 256, 512, whi, wlo);
    k_gemm_mma<<<gridH, 256, SMEM_GEMM>>>(ahi, alo, 256, whi, wlo, h, 512, nullptr, N_NODES);
    k_agg_init <<<gInit, T>>>((const float4*)h, dinv, (const float4*)b1, (float4*)a, total4);
    k_agg_edges<<<gEdge, T>>>(row, col, dinv, h, a, E);

    // layer 2: K=512
    k_split<<<(sH + T - 1) / T, T>>>((const float4*)a, 1, ahi, alo, sH);
    k_wconv<<<(512 * 512 + T - 1) / T, T>>>(W2, 512, 512, whi, wlo);
    k_gemm_mma<<<gridH, 256, SMEM_GEMM>>>(ahi, alo, 512, whi, wlo, h, 512, nullptr, N_NODES);
    k_agg_init <<<gInit, T>>>((const float4*)h, dinv, (const float4*)b2, (float4*)a, total4);
    k_agg_edges<<<gEdge, T>>>(row, col, dinv, h, a, E);

    // layer 3: K=512
    k_split<<<(sH + T - 1) / T, T>>>((const float4*)a, 1, ahi, alo, sH);
    k_wconv<<<(512 * 512 + T - 1) / T, T>>>(W3, 512, 512, whi, wlo);
    k_gemm_mma<<<gridH, 256, SMEM_GEMM>>>(ahi, alo, 512, whi, wlo, h, 512, nullptr, N_NODES);
    k_agg_init <<<gInit, T>>>((const float4*)h, dinv, (const float4*)b3, (float4*)a, total4);
    k_agg_edges<<<gEdge, T>>>(row, col, dinv, h, a, E);

    // final FC: K=512, Nout=256, bias
    k_split<<<(sH + T - 1) / T, T>>>((const float4*)a, 1, ahi, alo, sH);
    k_wconv<<<(512 * 256 + T - 1) / T, T>>>(Wfc, 512, 256, whi, wlo);
    k_gemm_mma<<<gridO, 256, SMEM_GEMM>>>(ahi, alo, 512, whi, wlo, (float*)d_out, 256, bfc, N_NODES);
}

// round 5
// speedup vs baseline: 2.1538x; 1.4762x over previous
#include <cuda_runtime.h>
#include <cuda_bf16.h>
#include <cstdint>

#define N_NODES 100000
#define N_PAD   100096          // 782 * 128
#define D_HID   512
#define E_MAX   800000

static __device__ __align__(16)  float g_dinv[N_NODES];
static __device__ __align__(256) float g_hp[(size_t)N_NODES * D_HID];     // h' = dinv * (A W)
static __device__ __align__(256) __nv_bfloat16 g_ahi[(size_t)N_PAD * D_HID];
static __device__ __align__(256) __nv_bfloat16 g_alo[(size_t)N_PAD * D_HID];
static __device__ __align__(256) __nv_bfloat16 g_whi[512 * 512];
static __device__ __align__(256) __nv_bfloat16 g_wlo[512 * 512];
static __device__ int g_row[E_MAX];
static __device__ int g_col[E_MAX];
static __device__ int g_ideg[N_NODES];
static __device__ int g_rowptr[N_NODES + 1];
static __device__ int g_cursor[N_NODES];
static __device__ int g_csrcol[E_MAX];
static __device__ int g_is32;

// ================================================================ helpers
__device__ __forceinline__ uint32_t smem_u32(const void* p) {
    uint32_t a;
    asm("{ .reg .u64 t; cvta.to.shared.u64 t, %1; cvt.u32.u64 %0, t; }" : "=r"(a) : "l"(p));
    return a;
}
__device__ __forceinline__ void cp16(uint32_t dst, const void* src) {
    asm volatile("cp.async.cg.shared.global [%0], [%1], 16;" :: "r"(dst), "l"(src) : "memory");
}
__device__ __forceinline__ void ldx4(uint32_t r[4], uint32_t addr) {
    asm volatile("ldmatrix.sync.aligned.m8n8.x4.shared.b16 {%0,%1,%2,%3}, [%4];"
                 : "=r"(r[0]), "=r"(r[1]), "=r"(r[2]), "=r"(r[3]) : "r"(addr));
}
__device__ __forceinline__ void mma_bf16(float c[4], const uint32_t a[4], uint32_t b0, uint32_t b1) {
    asm volatile("mma.sync.aligned.m16n8k16.row.col.f32.bf16.bf16.f32 "
                 "{%0,%1,%2,%3}, {%4,%5,%6,%7}, {%8,%9}, {%0,%1,%2,%3};"
                 : "+f"(c[0]), "+f"(c[1]), "+f"(c[2]), "+f"(c[3])
                 : "r"(a[0]), "r"(a[1]), "r"(a[2]), "r"(a[3]), "r"(b0), "r"(b1));
}
// fp32 -> (hi = trunc top16 exact, lo = rn(residual))
__device__ __forceinline__ void split4(float4 v, uint2& hiw, uint2& low) {
    uint32_t ux = __float_as_uint(v.x), uy = __float_as_uint(v.y);
    uint32_t uz = __float_as_uint(v.z), uw = __float_as_uint(v.w);
    hiw.x = __byte_perm(ux, uy, 0x7632);
    hiw.y = __byte_perm(uz, uw, 0x7632);
    float rx = v.x - __uint_as_float(ux & 0xFFFF0000u);
    float ry = v.y - __uint_as_float(uy & 0xFFFF0000u);
    float rz = v.z - __uint_as_float(uz & 0xFFFF0000u);
    float rw = v.w - __uint_as_float(uw & 0xFFFF0000u);
    __nv_bfloat162 l01 = __floats2bfloat162_rn(rx, ry);
    __nv_bfloat162 l23 = __floats2bfloat162_rn(rz, rw);
    low.x = *(uint32_t*)&l01;
    low.y = *(uint32_t*)&l23;
}

// ================================================================ bf16 MMA GEMM
// C[nrows,Nout] = rowscale? * (Ahi+Alo)[.,K] @ (Whi+Wlo)[Nout,K]^T (+bias)
// 3-stage cp.async pipeline, BK=32, 256 threads, 128x128 block.
__global__ __launch_bounds__(256, 1)
void k_gemm_mma(const __nv_bfloat16* __restrict__ Ahi, const __nv_bfloat16* __restrict__ Alo,
                int K,
                const __nv_bfloat16* __restrict__ Whi, const __nv_bfloat16* __restrict__ Wlo,
                float* __restrict__ C, int Nout, const float* __restrict__ bias,
                const float* __restrict__ rowscale, int nrows) {
    extern __shared__ char smem[];
    const uint32_t sb = smem_u32(smem);
    const int MTX = 10240;           // 128 rows * 80 B
    const int STAGE = 4 * MTX;       // 40 KB

    const int tid = threadIdx.x, wid = tid >> 5, lane = tid & 31;
    const int wm = wid & 3, wn = wid >> 2;
    const int brow = blockIdx.x * 128, bcol = blockIdx.y * 128;
    const int nit = K >> 5;

    const int c0 = tid * 2, c1 = tid * 2 + 1;
    const int r0 = c0 >> 2, k16_0 = c0 & 3;
    const int r1 = c1 >> 2, k16_1 = c1 & 3;

    const int g = lane >> 3, lr = lane & 7;
    const uint32_t a_row = (uint32_t)(wm * 32 + (g & 1) * 8 + lr);
    const uint32_t b_row = (uint32_t)(wn * 64 + (g & 1) * 8 + lr);
    const uint32_t kg = (uint32_t)((g >> 1) * 16);

    float acc[2][8][4];
#pragma unroll
    for (int m = 0; m < 2; m++)
#pragma unroll
        for (int n = 0; n < 8; n++)
#pragma unroll
            for (int v = 0; v < 4; v++) acc[m][n][v] = 0.f;

#define LOAD_STAGE(I) do {                                                            \
    uint32_t _d = sb + ((I) % 3) * STAGE; int _k0 = (I) * 32;                         \
    cp16(_d + r0 * 80 + k16_0 * 16,           Ahi + (size_t)(brow + r0) * K + _k0 + k16_0 * 8); \
    cp16(_d + r1 * 80 + k16_1 * 16,           Ahi + (size_t)(brow + r1) * K + _k0 + k16_1 * 8); \
    cp16(_d + MTX + r0 * 80 + k16_0 * 16,     Alo + (size_t)(brow + r0) * K + _k0 + k16_0 * 8); \
    cp16(_d + MTX + r1 * 80 + k16_1 * 16,     Alo + (size_t)(brow + r1) * K + _k0 + k16_1 * 8); \
    cp16(_d + 2 * MTX + r0 * 80 + k16_0 * 16, Whi + (size_t)(bcol + r0) * K + _k0 + k16_0 * 8); \
    cp16(_d + 2 * MTX + r1 * 80 + k16_1 * 16, Whi + (size_t)(bcol + r1) * K + _k0 + k16_1 * 8); \
    cp16(_d + 3 * MTX + r0 * 80 + k16_0 * 16, Wlo + (size_t)(bcol + r0) * K + _k0 + k16_0 * 8); \
    cp16(_d + 3 * MTX + r1 * 80 + k16_1 * 16, Wlo + (size_t)(bcol + r1) * K + _k0 + k16_1 * 8); \
    asm volatile("cp.async.commit_group;" ::: "memory");                              \
} while (0)

    LOAD_STAGE(0);
    LOAD_STAGE(1);

    for (int i = 0; i < nit; i++) {
        if (i + 2 < nit) {
            LOAD_STAGE(i + 2);
            asm volatile("cp.async.wait_group 2;" ::: "memory");
        } else {
            asm volatile("cp.async.wait_group 0;" ::: "memory");
        }
        __syncthreads();

        const uint32_t base = sb + (i % 3) * STAGE;
#pragma unroll
        for (int kst = 0; kst < 2; kst++) {
            const uint32_t acol = kg + kst * 32;
            uint32_t ah[2][4], al[2][4], bh[4][4], bl[4][4];
#pragma unroll
            for (int m = 0; m < 2; m++) {
                uint32_t aa = base + (a_row + m * 16) * 80 + acol;
                ldx4(ah[m], aa);
                ldx4(al[m], aa + MTX);
            }
#pragma unroll
            for (int p = 0; p < 4; p++) {
                uint32_t ba = base + 2 * MTX + (b_row + p * 16) * 80 + acol;
                ldx4(bh[p], ba);
                ldx4(bl[p], ba + MTX);
            }
#pragma unroll
            for (int m = 0; m < 2; m++)
#pragma unroll
                for (int p = 0; p < 4; p++)
#pragma unroll
                    for (int s = 0; s < 2; s++) {
                        float* cc = acc[m][p * 2 + s];
                        mma_bf16(cc, ah[m], bh[p][s], bh[p][s + 2]);
                        mma_bf16(cc, ah[m], bl[p][s], bl[p][s + 2]);
                        mma_bf16(cc, al[m], bh[p][s], bh[p][s + 2]);
                    }
        }
        __syncthreads();
    }
#undef LOAD_STAGE

    const int q = lane >> 2, qt = lane & 3;
#pragma unroll
    for (int m = 0; m < 2; m++) {
        int row = brow + wm * 32 + m * 16 + q;
        float sc0 = 1.f, sc1 = 1.f;
        if (rowscale) {
            if (row < nrows)     sc0 = rowscale[row];
            if (row + 8 < nrows) sc1 = rowscale[row + 8];
        }
#pragma unroll
        for (int n = 0; n < 8; n++) {
            int colb = bcol + wn * 64 + n * 8 + qt * 2;
            float* cc = acc[m][n];
            float bx = 0.f, by = 0.f;
            if (bias) { bx = bias[colb]; by = bias[colb + 1]; }
            if (row < nrows)
                *(float2*)(C + (size_t)row * Nout + colb) =
                    make_float2(fmaf(cc[0], sc0, bx), fmaf(cc[1], sc0, by));
            if (row + 8 < nrows)
                *(float2*)(C + (size_t)(row + 8) * Nout + colb) =
                    make_float2(fmaf(cc[2], sc1, bx), fmaf(cc[3], sc1, by));
        }
    }
}

// ================================================================ CSR pull aggregation
// warp per node: acc = h'[n] + sum_{c in N(n)} h'[c];  out = relu(dinv[n]*acc + b)
// -> split to bf16 hi/lo, written directly as next GEMM's A.
__global__ __launch_bounds__(256)
void k_agg_csr(const int* __restrict__ rowptr, const int* __restrict__ csrcol,
               const float* __restrict__ dinv, const float* __restrict__ hp,
               const float4* __restrict__ bias,
               __nv_bfloat16* __restrict__ hi, __nv_bfloat16* __restrict__ lo) {
    int gw = (int)((blockIdx.x * blockDim.x + threadIdx.x) >> 5);
    int lane = threadIdx.x & 31;
    if (gw >= N_NODES) return;
    int s = __ldg(rowptr + gw), e = __ldg(rowptr + gw + 1);

    const float4* self = (const float4*)(hp + (size_t)gw * D_HID);
    float4 acc[4];
#pragma unroll
    for (int i = 0; i < 4; i++) acc[i] = __ldg(self + lane + i * 32);

    int j = s;
    for (; j + 1 < e; j += 2) {
        int c0 = __ldg(csrcol + j), c1 = __ldg(csrcol + j + 1);
        const float4* s0 = (const float4*)(hp + (size_t)c0 * D_HID);
        const float4* s1 = (const float4*)(hp + (size_t)c1 * D_HID);
        float4 v0[4], v1[4];
#pragma unroll
        for (int i = 0; i < 4; i++) { v0[i] = __ldg(s0 + lane + i * 32); v1[i] = __ldg(s1 + lane + i * 32); }
#pragma unroll
        for (int i = 0; i < 4; i++) {
            acc[i].x += v0[i].x + v1[i].x; acc[i].y += v0[i].y + v1[i].y;
            acc[i].z += v0[i].z + v1[i].z; acc[i].w += v0[i].w + v1[i].w;
        }
    }
    if (j < e) {
        int c = __ldg(csrcol + j);
        const float4* sv = (const float4*)(hp + (size_t)c * D_HID);
#pragma unroll
        for (int i = 0; i < 4; i++) {
            float4 v = __ldg(sv + lane + i * 32);
            acc[i].x += v.x; acc[i].y += v.y; acc[i].z += v.z; acc[i].w += v.w;
        }
    }

    float d = dinv[gw];
    size_t obase = (size_t)gw * D_HID;
#pragma unroll
    for (int i = 0; i < 4; i++) {
        float4 b = __ldg(bias + lane + i * 32);
        float4 v;
        v.x = fmaxf(fmaf(d, acc[i].x, b.x), 0.f);
        v.y = fmaxf(fmaf(d, acc[i].y, b.y), 0.f);
        v.z = fmaxf(fmaf(d, acc[i].z, b.z), 0.f);
        v.w = fmaxf(fmaf(d, acc[i].w, b.w), 0.f);
        uint2 hw, lw;
        split4(v, hw, lw);
        *(uint2*)(hi + obase + (size_t)(lane + i * 32) * 4) = hw;
        *(uint2*)(lo + obase + (size_t)(lane + i * 32) * 4) = lw;
    }
}

// ================================================================ conversions
__global__ void k_split(const float4* __restrict__ A,
                        __nv_bfloat16* __restrict__ hi, __nv_bfloat16* __restrict__ lo, int total4) {
    int i = blockIdx.x * blockDim.x + threadIdx.x;
    if (i >= total4) return;
    uint2 hw, lw;
    split4(A[i], hw, lw);
    *(uint2*)(hi + (size_t)i * 4) = hw;
    *(uint2*)(lo + (size_t)i * 4) = lw;
}

__global__ void k_wconv(const float* __restrict__ W, int K, int Nout,
                        __nv_bfloat16* __restrict__ whi, __nv_bfloat16* __restrict__ wlo) {
    int idx = blockIdx.x * blockDim.x + threadIdx.x;
    if (idx >= K * Nout) return;
    int k = idx / Nout, n = idx - k * Nout;
    float v = W[idx];
    uint32_t u = __float_as_uint(v);
    float h = __uint_as_float(u & 0xFFFF0000u);
    ushort hs = (ushort)(u >> 16);
    whi[(size_t)n * K + k] = *reinterpret_cast<__nv_bfloat16*>(&hs);
    wlo[(size_t)n * K + k] = __float2bfloat16_rn(v - h);
}

// ================================================================ graph prep
__global__ void k_zero_flag() { g_is32 = 0; }
__global__ void k_detect(const long long* __restrict__ p, int n) {
    int i = blockIdx.x * blockDim.x + threadIdx.x;
    if (i < n) {
        long long v = p[i];
        if (v < 0 || v >= N_NODES) atomicOr(&g_is32, 1);
    }
}
__global__ void k_convert(const void* __restrict__ ei, int E,
                          int* __restrict__ row, int* __restrict__ col) {
    int i = blockIdx.x * blockDim.x + threadIdx.x;
    if (i >= E) return;
    if (g_is32) {
        const int* p = (const int*)ei;
        row[i] = p[i]; col[i] = p[E + i];
    } else {
        const long long* p = (const long long*)ei;
        row[i] = (int)p[i]; col[i] = (int)p[E + i];
    }
}
__global__ void k_zeroi(int* __restrict__ p, int n) {
    int i = blockIdx.x * blockDim.x + threadIdx.x;
    if (i < n) p[i] = 0;
}
__global__ void k_ideg(const int* __restrict__ rows, int* __restrict__ deg, int E) {
    int i = blockIdx.x * blockDim.x + threadIdx.x;
    if (i < E) atomicAdd(&deg[rows[i]], 1);
}
__global__ void k_dinv(const int* __restrict__ ideg, float* __restrict__ dinv, int n) {
    int i = blockIdx.x * blockDim.x + threadIdx.x;
    if (i < n) dinv[i] = rsqrtf((float)(ideg[i] + 1));
}
// single-block exclusive scan of deg[n] -> rowptr (+cursor copy), rowptr[n] = total
__global__ __launch_bounds__(1024)
void k_scan(const int* __restrict__ deg, int* __restrict__ rowptr,
            int* __restrict__ cursor, int n) {
    __shared__ int warpsum[32];
    __shared__ int carry, total;
    int tid = threadIdx.x, w = tid >> 5, lane = tid & 31;
    if (tid == 0) carry = 0;
    __syncthreads();
    for (int base = 0; base < n; base += 1024) {
        int idx = base + tid;
        int v = (idx < n) ? deg[idx] : 0;
        int x = v;
#pragma unroll
        for (int o = 1; o < 32; o <<= 1) {
            int y = __shfl_up_sync(0xFFFFFFFFu, x, o);
            if (lane >= o) x += y;
        }
        if (lane == 31) warpsum[w] = x;
        __syncthreads();
        if (tid == 0) {
            int s = 0;
            for (int i = 0; i < 32; i++) { int t = warpsum[i]; warpsum[i] = s; s += t; }
            total = s;
        }
        __syncthreads();
        int excl = carry + warpsum[w] + x - v;
        if (idx < n) { rowptr[idx] = excl; cursor[idx] = excl; }
        __syncthreads();
        if (tid == 0) carry += total;
        __syncthreads();
    }
    if (threadIdx.x == 0) rowptr[n] = carry;
}
__global__ void k_csr_scatter(const int* __restrict__ row, const int* __restrict__ col,
                              int* __restrict__ cursor, int* __restrict__ csrcol, int E) {
    int i = blockIdx.x * blockDim.x + threadIdx.x;
    if (i >= E) return;
    int p = atomicAdd(&cursor[row[i]], 1);
    csrcol[p] = col[i];
}

// ================================================================ launch
extern "C" void kernel_launch(void* const* d_in, const int* in_sizes, int n_in,
                              void* d_out, int out_size) {
    const float* x   = (const float*)d_in[0];
    const void*  ei  = d_in[1];
    const float* W1  = (const float*)d_in[2];
    const float* b1  = (const float*)d_in[3];
    const float* W2  = (const float*)d_in[4];
    const float* b2  = (const float*)d_in[5];
    const float* W3  = (const float*)d_in[6];
    const float* b3  = (const float*)d_in[7];
    const float* Wfc = (const float*)d_in[8];
    const float* bfc = (const float*)d_in[9];
    int E = in_sizes[1] / 2;
    if (E > E_MAX) E = E_MAX;

    float *dinv, *hp;
    int *row, *col, *ideg, *rowptr, *cursor, *csrcol;
    __nv_bfloat16 *ahi, *alo, *whi, *wlo;
    cudaGetSymbolAddress((void**)&dinv,   g_dinv);
    cudaGetSymbolAddress((void**)&hp,     g_hp);
    cudaGetSymbolAddress((void**)&row,    g_row);
    cudaGetSymbolAddress((void**)&col,    g_col);
    cudaGetSymbolAddress((void**)&ideg,   g_ideg);
    cudaGetSymbolAddress((void**)&rowptr, g_rowptr);
    cudaGetSymbolAddress((void**)&cursor, g_cursor);
    cudaGetSymbolAddress((void**)&csrcol, g_csrcol);
    cudaGetSymbolAddress((void**)&ahi,    g_ahi);
    cudaGetSymbolAddress((void**)&alo,    g_alo);
    cudaGetSymbolAddress((void**)&whi,    g_whi);
    cudaGetSymbolAddress((void**)&wlo,    g_wlo);

    const int SMEM_GEMM = 3 * 4 * 10240;  // 120 KB
    cudaFuncSetAttribute(k_gemm_mma, cudaFuncAttributeMaxDynamicSharedMemorySize, SMEM_GEMM);

    const int T = 256;
    int gE = (E + T - 1) / T;
    int gN = (N_NODES + T - 1) / T;

    // edge index dtype detect + int32 scratch
    k_zero_flag<<<1, 1>>>();
    k_detect <<<gE, T>>>((const long long*)ei, E);
    k_convert<<<gE, T>>>(ei, E, row, col);

    // degree, dinv, CSR
    k_zeroi<<<gN, T>>>(ideg, N_NODES);
    k_ideg <<<gE, T>>>(row, ideg, E);
    k_dinv <<<gN, T>>>(ideg, dinv, N_NODES);
    k_scan <<<1, 1024>>>(ideg, rowptr, cursor, N_NODES);
    k_csr_scatter<<<gE, T>>>(row, col, cursor, csrcol, E);

    dim3 gridH((N_NODES + 127) / 128, 4);
    dim3 gridO((N_NODES + 127) / 128, 2);
    int gAgg = (int)(((long long)N_NODES * 32 + T - 1) / T);
    int s1 = N_NODES * 256 / 4;

    // layer 1: K=256
    k_split<<<(s1 + T - 1) / T, T>>>((const float4*)x, ahi, alo, s1);
    k_wconv<<<(256 * 512 + T - 1) / T, T>>>(W1, 256, 512, whi, wlo);
    k_gemm_mma<<<gridH, 256, SMEM_GEMM>>>(ahi, alo, 256, whi, wlo, hp, 512, nullptr, dinv, N_NODES);
    k_agg_csr<<<gAgg, T>>>(rowptr, csrcol, dinv, hp, (const float4*)b1, ahi, alo);

    // layer 2: K=512
    k_wconv<<<(512 * 512 + T - 1) / T, T>>>(W2, 512, 512, whi, wlo);
    k_gemm_mma<<<gridH, 256, SMEM_GEMM>>>(ahi, alo, 512, whi, wlo, hp, 512, nullptr, dinv, N_NODES);
    k_agg_csr<<<gAgg, T>>>(rowptr, csrcol, dinv, hp, (const float4*)b2, ahi, alo);

    // layer 3: K=512
    k_wconv<<<(512 * 512 + T - 1) / T, T>>>(W3, 512, 512, whi, wlo);
    k_gemm_mma<<<gridH, 256, SMEM_GEMM>>>(ahi, alo, 512, whi, wlo, hp, 512, nullptr, dinv, N_NODES);
    k_agg_csr<<<gAgg, T>>>(rowptr, csrcol, dinv, hp, (const float4*)b3, ahi, alo);

    // final FC: K=512, Nout=256, bias, no rowscale
    k_wconv<<<(512 * 256 + T - 1) / T, T>>>(Wfc, 512, 256, whi, wlo);
    k_gemm_mma<<<gridO, 256, SMEM_GEMM>>>(ahi, alo, 512, whi, wlo, (float*)d_out, 256, bfc, nullptr, N_NODES);
}

// round 6
// speedup vs baseline: 2.4371x; 1.1315x over previous
#include <cuda_runtime.h>
#include <cuda_bf16.h>
#include <cstdint>

#define N_NODES 100000
#define D_HID   512
#define E_MAX   800000

// weight segment offsets in g_whi/g_wlo
#define W_OFF_L1 0
#define W_OFF_L2 131072
#define W_OFF_L3 393216
#define W_OFF_FC 655360
#define W_TOTAL  786432

static __device__ __align__(16)  float g_dinv[N_NODES];
static __device__ __align__(256) float g_hp[(size_t)N_NODES * D_HID];
static __device__ __align__(256) __nv_bfloat16 g_ahi[(size_t)N_NODES * D_HID];
static __device__ __align__(256) __nv_bfloat16 g_alo[(size_t)N_NODES * D_HID];
static __device__ __align__(256) __nv_bfloat16 g_whi[W_TOTAL];
static __device__ __align__(256) __nv_bfloat16 g_wlo[W_TOTAL];
static __device__ int g_row[E_MAX];
static __device__ int g_col[E_MAX];
static __device__ int g_ideg[N_NODES];
static __device__ int g_rowptr[N_NODES + 1];
static __device__ int g_cursor[N_NODES];
static __device__ int g_csrcol[E_MAX];
static __device__ int g_is32;

// ================================================================ helpers
__device__ __forceinline__ uint32_t smem_u32(const void* p) {
    uint32_t a;
    asm("{ .reg .u64 t; cvta.to.shared.u64 t, %1; cvt.u32.u64 %0, t; }" : "=r"(a) : "l"(p));
    return a;
}
__device__ __forceinline__ void cp16(uint32_t dst, const void* src) {
    asm volatile("cp.async.cg.shared.global [%0], [%1], 16;" :: "r"(dst), "l"(src) : "memory");
}
__device__ __forceinline__ void ldx4(uint32_t r[4], uint32_t addr) {
    asm volatile("ldmatrix.sync.aligned.m8n8.x4.shared.b16 {%0,%1,%2,%3}, [%4];"
                 : "=r"(r[0]), "=r"(r[1]), "=r"(r[2]), "=r"(r[3]) : "r"(addr));
}
__device__ __forceinline__ void mma_bf16(float c[4], const uint32_t a[4], uint32_t b0, uint32_t b1) {
    asm volatile("mma.sync.aligned.m16n8k16.row.col.f32.bf16.bf16.f32 "
                 "{%0,%1,%2,%3}, {%4,%5,%6,%7}, {%8,%9}, {%0,%1,%2,%3};"
                 : "+f"(c[0]), "+f"(c[1]), "+f"(c[2]), "+f"(c[3])
                 : "r"(a[0]), "r"(a[1]), "r"(a[2]), "r"(a[3]), "r"(b0), "r"(b1));
}
__device__ __forceinline__ void split4(float4 v, uint2& hiw, uint2& low) {
    uint32_t ux = __float_as_uint(v.x), uy = __float_as_uint(v.y);
    uint32_t uz = __float_as_uint(v.z), uw = __float_as_uint(v.w);
    hiw.x = __byte_perm(ux, uy, 0x7632);
    hiw.y = __byte_perm(uz, uw, 0x7632);
    float rx = v.x - __uint_as_float(ux & 0xFFFF0000u);
    float ry = v.y - __uint_as_float(uy & 0xFFFF0000u);
    float rz = v.z - __uint_as_float(uz & 0xFFFF0000u);
    float rw = v.w - __uint_as_float(uw & 0xFFFF0000u);
    __nv_bfloat162 l01 = __floats2bfloat162_rn(rx, ry);
    __nv_bfloat162 l23 = __floats2bfloat162_rn(rz, rw);
    low.x = *(uint32_t*)&l01;
    low.y = *(uint32_t*)&l23;
}

// ================================================================ bf16 MMA GEMM
// C[nrows,Nout] = (Ahi+Alo)[.,K] @ (Whi+Wlo)[Nout,K]^T (+bias)
// 2-stage cp.async pipeline, BK=32, 256 threads, 128x128 block, 2 CTA/SM.
__global__ __launch_bounds__(256, 2)
void k_gemm_mma(const __nv_bfloat16* __restrict__ Ahi, const __nv_bfloat16* __restrict__ Alo,
                int K,
                const __nv_bfloat16* __restrict__ Whi, const __nv_bfloat16* __restrict__ Wlo,
                float* __restrict__ C, int Nout, const float* __restrict__ bias, int nrows) {
    extern __shared__ char smem[];
    const uint32_t sb = smem_u32(smem);
    const int MTX = 10240;           // 128 rows * 80 B
    const int STAGE = 4 * MTX;       // 40 KB

    const int tid = threadIdx.x, wid = tid >> 5, lane = tid & 31;
    const int wm = wid & 3, wn = wid >> 2;
    const int brow = blockIdx.x * 128, bcol = blockIdx.y * 128;
    const int nit = K >> 5;

    const int c0 = tid * 2, c1 = tid * 2 + 1;
    const int r0 = c0 >> 2, k16_0 = c0 & 3;
    const int r1 = c1 >> 2, k16_1 = c1 & 3;

    const int g = lane >> 3, lr = lane & 7;
    const uint32_t a_row = (uint32_t)(wm * 32 + (g & 1) * 8 + lr);
    const uint32_t b_row = (uint32_t)(wn * 64 + (g & 1) * 8 + lr);
    const uint32_t kg = (uint32_t)((g >> 1) * 16);

    float acc[2][8][4];
#pragma unroll
    for (int m = 0; m < 2; m++)
#pragma unroll
        for (int n = 0; n < 8; n++)
#pragma unroll
            for (int v = 0; v < 4; v++) acc[m][n][v] = 0.f;

#define LOAD_STAGE(I) do {                                                            \
    uint32_t _d = sb + ((I) & 1) * STAGE; int _k0 = (I) * 32;                         \
    cp16(_d + r0 * 80 + k16_0 * 16,           Ahi + (size_t)(brow + r0) * K + _k0 + k16_0 * 8); \
    cp16(_d + r1 * 80 + k16_1 * 16,           Ahi + (size_t)(brow + r1) * K + _k0 + k16_1 * 8); \
    cp16(_d + MTX + r0 * 80 + k16_0 * 16,     Alo + (size_t)(brow + r0) * K + _k0 + k16_0 * 8); \
    cp16(_d + MTX + r1 * 80 + k16_1 * 16,     Alo + (size_t)(brow + r1) * K + _k0 + k16_1 * 8); \
    cp16(_d + 2 * MTX + r0 * 80 + k16_0 * 16, Whi + (size_t)(bcol + r0) * K + _k0 + k16_0 * 8); \
    cp16(_d + 2 * MTX + r1 * 80 + k16_1 * 16, Whi + (size_t)(bcol + r1) * K + _k0 + k16_1 * 8); \
    cp16(_d + 3 * MTX + r0 * 80 + k16_0 * 16, Wlo + (size_t)(bcol + r0) * K + _k0 + k16_0 * 8); \
    cp16(_d + 3 * MTX + r1 * 80 + k16_1 * 16, Wlo + (size_t)(bcol + r1) * K + _k0 + k16_1 * 8); \
    asm volatile("cp.async.commit_group;" ::: "memory");                              \
} while (0)

    LOAD_STAGE(0);

    for (int i = 0; i < nit; i++) {
        if (i + 1 < nit) {
            LOAD_STAGE(i + 1);
            asm volatile("cp.async.wait_group 1;" ::: "memory");
        } else {
            asm volatile("cp.async.wait_group 0;" ::: "memory");
        }
        __syncthreads();

        const uint32_t base = sb + (i & 1) * STAGE;
#pragma unroll
        for (int kst = 0; kst < 2; kst++) {
            const uint32_t acol = kg + kst * 32;
            uint32_t ah[2][4], al[2][4];
#pragma unroll
            for (int m = 0; m < 2; m++) {
                uint32_t aa = base + (a_row + m * 16) * 80 + acol;
                ldx4(ah[m], aa);
                ldx4(al[m], aa + MTX);
            }
#pragma unroll
            for (int p = 0; p < 4; p++) {
                uint32_t bh[4], bl[4];
                uint32_t ba = base + 2 * MTX + (b_row + p * 16) * 80 + acol;
                ldx4(bh, ba);
                ldx4(bl, ba + MTX);
#pragma unroll
                for (int m = 0; m < 2; m++)
#pragma unroll
                    for (int s = 0; s < 2; s++) {
                        float* cc = acc[m][p * 2 + s];
                        mma_bf16(cc, ah[m], bh[s], bh[s + 2]);
                        mma_bf16(cc, ah[m], bl[s], bl[s + 2]);
                        mma_bf16(cc, al[m], bh[s], bh[s + 2]);
                    }
            }
        }
        __syncthreads();
    }
#undef LOAD_STAGE

    const int q = lane >> 2, qt = lane & 3;
#pragma unroll
    for (int m = 0; m < 2; m++) {
        int row = brow + wm * 32 + m * 16 + q;
#pragma unroll
        for (int n = 0; n < 8; n++) {
            int colb = bcol + wn * 64 + n * 8 + qt * 2;
            float* cc = acc[m][n];
            float bx = 0.f, by = 0.f;
            if (bias) { bx = bias[colb]; by = bias[colb + 1]; }
            if (row < nrows)
                *(float2*)(C + (size_t)row * Nout + colb) = make_float2(cc[0] + bx, cc[1] + by);
            if (row + 8 < nrows)
                *(float2*)(C + (size_t)(row + 8) * Nout + colb) = make_float2(cc[2] + bx, cc[3] + by);
        }
    }
}

// ================================================================ CSR pull aggregation
// One 256-col pass: acc = dinv[n]*hp[n,cols] + sum_c dinv[c]*hp[c,cols]
// out = relu(dinv[n]*acc + b) -> bf16 hi/lo
__global__ __launch_bounds__(256)
void k_agg_csr(const int* __restrict__ rowptr, const int* __restrict__ csrcol,
               const float* __restrict__ dinv, const float* __restrict__ hp,
               const float* __restrict__ bias,
               __nv_bfloat16* __restrict__ hi, __nv_bfloat16* __restrict__ lo, int col_base) {
    int gw = (int)((blockIdx.x * blockDim.x + threadIdx.x) >> 5);
    int lane = threadIdx.x & 31;
    if (gw >= N_NODES) return;
    int s = __ldg(rowptr + gw), e = __ldg(rowptr + gw + 1);
    const int cb4 = col_base >> 2;   // float4 offset

    float dself = __ldg(dinv + gw);
    const float4* self = (const float4*)(hp + (size_t)gw * D_HID) + cb4;
    float4 acc[2];
#pragma unroll
    for (int i = 0; i < 2; i++) {
        float4 v = __ldg(self + lane + i * 32);
        acc[i] = make_float4(dself * v.x, dself * v.y, dself * v.z, dself * v.w);
    }

    int j = s;
    for (; j + 1 < e; j += 2) {
        int c0 = __ldg(csrcol + j), c1 = __ldg(csrcol + j + 1);
        float w0 = __ldg(dinv + c0), w1 = __ldg(dinv + c1);
        const float4* s0 = (const float4*)(hp + (size_t)c0 * D_HID) + cb4;
        const float4* s1 = (const float4*)(hp + (size_t)c1 * D_HID) + cb4;
#pragma unroll
        for (int i = 0; i < 2; i++) {
            float4 v0 = __ldg(s0 + lane + i * 32);
            float4 v1 = __ldg(s1 + lane + i * 32);
            acc[i].x = fmaf(w0, v0.x, fmaf(w1, v1.x, acc[i].x));
            acc[i].y = fmaf(w0, v0.y, fmaf(w1, v1.y, acc[i].y));
            acc[i].z = fmaf(w0, v0.z, fmaf(w1, v1.z, acc[i].z));
            acc[i].w = fmaf(w0, v0.w, fmaf(w1, v1.w, acc[i].w));
        }
    }
    if (j < e) {
        int c = __ldg(csrcol + j);
        float w = __ldg(dinv + c);
        const float4* sv = (const float4*)(hp + (size_t)c * D_HID) + cb4;
#pragma unroll
        for (int i = 0; i < 2; i++) {
            float4 v = __ldg(sv + lane + i * 32);
            acc[i].x = fmaf(w, v.x, acc[i].x);
            acc[i].y = fmaf(w, v.y, acc[i].y);
            acc[i].z = fmaf(w, v.z, acc[i].z);
            acc[i].w = fmaf(w, v.w, acc[i].w);
        }
    }

    size_t obase = (size_t)gw * D_HID;
#pragma unroll
    for (int i = 0; i < 2; i++) {
        int f4 = cb4 + lane + i * 32;
        float4 b = __ldg((const float4*)bias + f4);
        float4 v;
        v.x = fmaxf(fmaf(dself, acc[i].x, b.x), 0.f);
        v.y = fmaxf(fmaf(dself, acc[i].y, b.y), 0.f);
        v.z = fmaxf(fmaf(dself, acc[i].z, b.z), 0.f);
        v.w = fmaxf(fmaf(dself, acc[i].w, b.w), 0.f);
        uint2 hw, lw;
        split4(v, hw, lw);
        *(uint2*)(hi + obase + (size_t)f4 * 4) = hw;
        *(uint2*)(lo + obase + (size_t)f4 * 4) = lw;
    }
}

// ================================================================ prep kernels
// zero flag + ideg, convert ALL weights fp32[K][Nout] -> bf16 hi/lo [Nout][K]
__global__ void k_prep_all(const float* __restrict__ W1, const float* __restrict__ W2,
                           const float* __restrict__ W3, const float* __restrict__ Wfc,
                           __nv_bfloat16* __restrict__ whi, __nv_bfloat16* __restrict__ wlo,
                           int* __restrict__ ideg) {
    int idx = blockIdx.x * blockDim.x + threadIdx.x;
    if (idx == 0) g_is32 = 0;
    if (idx < N_NODES) ideg[idx] = 0;
    if (idx >= W_TOTAL) return;
    const float* W; int K, Nout, base;
    if (idx < W_OFF_L2)      { W = W1;  K = 256; Nout = 512; base = W_OFF_L1; }
    else if (idx < W_OFF_L3) { W = W2;  K = 512; Nout = 512; base = W_OFF_L2; }
    else if (idx < W_OFF_FC) { W = W3;  K = 512; Nout = 512; base = W_OFF_L3; }
    else                     { W = Wfc; K = 512; Nout = 256; base = W_OFF_FC; }
    int local = idx - base;
    int k = local / Nout, n = local - k * Nout;
    float v = W[local];
    uint32_t u = __float_as_uint(v);
    float h = __uint_as_float(u & 0xFFFF0000u);
    ushort hs = (ushort)(u >> 16);
    whi[base + (size_t)n * K + k] = *reinterpret_cast<__nv_bfloat16*>(&hs);
    wlo[base + (size_t)n * K + k] = __float2bfloat16_rn(v - h);
}

__global__ void k_detect(const long long* __restrict__ p, int n) {
    int i = blockIdx.x * blockDim.x + threadIdx.x;
    if (i < n) {
        long long v = p[i];
        if (v < 0 || v >= N_NODES) atomicOr(&g_is32, 1);
    }
}
__global__ void k_split(const float4* __restrict__ A,
                        __nv_bfloat16* __restrict__ hi, __nv_bfloat16* __restrict__ lo, int total4) {
    int i = blockIdx.x * blockDim.x + threadIdx.x;
    if (i >= total4) return;
    uint2 hw, lw;
    split4(A[i], hw, lw);
    *(uint2*)(hi + (size_t)i * 4) = hw;
    *(uint2*)(lo + (size_t)i * 4) = lw;
}
__global__ void k_convert_count(const void* __restrict__ ei, int E,
                                int* __restrict__ row, int* __restrict__ col,
                                int* __restrict__ ideg) {
    int i = blockIdx.x * blockDim.x + threadIdx.x;
    if (i >= E) return;
    int r, c;
    if (g_is32) {
        const int* p = (const int*)ei;
        r = p[i]; c = p[E + i];
    } else {
        const long long* p = (const long long*)ei;
        r = (int)p[i]; c = (int)p[E + i];
    }
    row[i] = r; col[i] = c;
    atomicAdd(&ideg[r], 1);
}
// exclusive scan of ideg -> rowptr/cursor, plus dinv = rsqrt(deg+1)
__global__ __launch_bounds__(1024)
void k_scan(const int* __restrict__ deg, int* __restrict__ rowptr,
            int* __restrict__ cursor, float* __restrict__ dinv, int n) {
    __shared__ int warpsum[32];
    __shared__ int carry, total;
    int tid = threadIdx.x, w = tid >> 5, lane = tid & 31;
    if (tid == 0) carry = 0;
    __syncthreads();
    for (int base = 0; base < n; base += 1024) {
        int idx = base + tid;
        int v = (idx < n) ? deg[idx] : 0;
        if (idx < n) dinv[idx] = rsqrtf((float)(v + 1));
        int x = v;
#pragma unroll
        for (int o = 1; o < 32; o <<= 1) {
            int y = __shfl_up_sync(0xFFFFFFFFu, x, o);
            if (lane >= o) x += y;
        }
        if (lane == 31) warpsum[w] = x;
        __syncthreads();
        if (tid == 0) {
            int s = 0;
            for (int i = 0; i < 32; i++) { int t = warpsum[i]; warpsum[i] = s; s += t; }
            total = s;
        }
        __syncthreads();
        int excl = carry + warpsum[w] + x - v;
        if (idx < n) { rowptr[idx] = excl; cursor[idx] = excl; }
        __syncthreads();
        if (tid == 0) carry += total;
        __syncthreads();
    }
    if (threadIdx.x == 0) rowptr[n] = carry;
}
__global__ void k_csr_scatter(const int* __restrict__ row, const int* __restrict__ col,
                              int* __restrict__ cursor, int* __restrict__ csrcol, int E) {
    int i = blockIdx.x * blockDim.x + threadIdx.x;
    if (i >= E) return;
    int p = atomicAdd(&cursor[row[i]], 1);
    csrcol[p] = col[i];
}

// ================================================================ launch
extern "C" void kernel_launch(void* const* d_in, const int* in_sizes, int n_in,
                              void* d_out, int out_size) {
    const float* x   = (const float*)d_in[0];
    const void*  ei  = d_in[1];
    const float* W1  = (const float*)d_in[2];
    const float* b1  = (const float*)d_in[3];
    const float* W2  = (const float*)d_in[4];
    const float* b2  = (const float*)d_in[5];
    const float* W3  = (const float*)d_in[6];
    const float* b3  = (const float*)d_in[7];
    const float* Wfc = (const float*)d_in[8];
    const float* bfc = (const float*)d_in[9];
    int E = in_sizes[1] / 2;
    if (E > E_MAX) E = E_MAX;

    float *dinv, *hp;
    int *row, *col, *ideg, *rowptr, *cursor, *csrcol;
    __nv_bfloat16 *ahi, *alo, *whi, *wlo;
    cudaGetSymbolAddress((void**)&dinv,   g_dinv);
    cudaGetSymbolAddress((void**)&hp,     g_hp);
    cudaGetSymbolAddress((void**)&row,    g_row);
    cudaGetSymbolAddress((void**)&col,    g_col);
    cudaGetSymbolAddress((void**)&ideg,   g_ideg);
    cudaGetSymbolAddress((void**)&rowptr, g_rowptr);
    cudaGetSymbolAddress((void**)&cursor, g_cursor);
    cudaGetSymbolAddress((void**)&csrcol, g_csrcol);
    cudaGetSymbolAddress((void**)&ahi,    g_ahi);
    cudaGetSymbolAddress((void**)&alo,    g_alo);
    cudaGetSymbolAddress((void**)&whi,    g_whi);
    cudaGetSymbolAddress((void**)&wlo,    g_wlo);

    const int SMEM_GEMM = 2 * 4 * 10240;  // 80 KB
    cudaFuncSetAttribute(k_gemm_mma, cudaFuncAttributeMaxDynamicSharedMemorySize, SMEM_GEMM);

    const int T = 256;
    int gE = (E + T - 1) / T;
    int s1 = N_NODES * 256 / 4;

    dim3 gridH((N_NODES + 127) / 128, 4);
    dim3 gridO((N_NODES + 127) / 128, 2);
    int gAgg = (int)(((long long)N_NODES * 32 + T - 1) / T);

    // 1. weights + zero ideg/flag
    k_prep_all<<<(W_TOTAL + T - 1) / T, T>>>(W1, W2, W3, Wfc, whi, wlo, ideg);
    // 2. dtype detect
    k_detect<<<gE, T>>>((const long long*)ei, E);
    // 3. split x
    k_split<<<(s1 + T - 1) / T, T>>>((const float4*)x, ahi, alo, s1);
    // 4. layer-1 GEMM (profiled launch)
    k_gemm_mma<<<gridH, 256, SMEM_GEMM>>>(ahi, alo, 256, whi + W_OFF_L1, wlo + W_OFF_L1,
                                          hp, 512, nullptr, N_NODES);
    // 5-7. graph prep
    k_convert_count<<<gE, T>>>(ei, E, row, col, ideg);
    k_scan<<<1, 1024>>>(ideg, rowptr, cursor, dinv, N_NODES);
    k_csr_scatter<<<gE, T>>>(row, col, cursor, csrcol, E);

    // layer 1 agg (two 256-col passes)
    k_agg_csr<<<gAgg, T>>>(rowptr, csrcol, dinv, hp, b1, ahi, alo, 0);
    k_agg_csr<<<gAgg, T>>>(rowptr, csrcol, dinv, hp, b1, ahi, alo, 256);

    // layer 2
    k_gemm_mma<<<gridH, 256, SMEM_GEMM>>>(ahi, alo, 512, whi + W_OFF_L2, wlo + W_OFF_L2,
                                          hp, 512, nullptr, N_NODES);
    k_agg_csr<<<gAgg, T>>>(rowptr, csrcol, dinv, hp, b2, ahi, alo, 0);
    k_agg_csr<<<gAgg, T>>>(rowptr, csrcol, dinv, hp, b2, ahi, alo, 256);

    // layer 3
    k_gemm_mma<<<gridH, 256, SMEM_GEMM>>>(ahi, alo, 512, whi + W_OFF_L3, wlo + W_OFF_L3,
                                          hp, 512, nullptr, N_NODES);
    k_agg_csr<<<gAgg, T>>>(rowptr, csrcol, dinv, hp, b3, ahi, alo, 0);
    k_agg_csr<<<gAgg, T>>>(rowptr, csrcol, dinv, hp, b3, ahi, alo, 256);

    // final FC
    k_gemm_mma<<<gridO, 256, SMEM_GEMM>>>(ahi, alo, 512, whi + W_OFF_FC, wlo + W_OFF_FC,
                                          (float*)d_out, 256, bfc, N_NODES);
}

// round 7
// speedup vs baseline: 2.4428x; 1.0023x over previous
#include <cuda_runtime.h>
#include <cuda_bf16.h>
#include <cstdint>

#define N_NODES 100000
#define D_HID   512
#define E_MAX   800000

// weight segment offsets in g_whi/g_wlo
#define W_OFF_L1 0
#define W_OFF_L2 131072
#define W_OFF_L3 393216
#define W_OFF_FC 655360
#define W_TOTAL  786432

static __device__ __align__(16)  float g_dinv[N_NODES];
static __device__ __align__(256) float g_hp[(size_t)N_NODES * D_HID];
static __device__ __align__(256) __nv_bfloat16 g_ahi[(size_t)N_NODES * D_HID];
static __device__ __align__(256) __nv_bfloat16 g_alo[(size_t)N_NODES * D_HID];
static __device__ __align__(256) __nv_bfloat16 g_whi[W_TOTAL];
static __device__ __align__(256) __nv_bfloat16 g_wlo[W_TOTAL];
static __device__ int g_row[E_MAX];
static __device__ int g_col[E_MAX];
static __device__ int g_ideg[N_NODES];
static __device__ int g_rowptr[N_NODES + 1];
static __device__ int g_cursor[N_NODES];
static __device__ int g_csrcol[E_MAX];
static __device__ int g_is32;

// ================================================================ helpers
__device__ __forceinline__ uint32_t smem_u32(const void* p) {
    uint32_t a;
    asm("{ .reg .u64 t; cvta.to.shared.u64 t, %1; cvt.u32.u64 %0, t; }" : "=r"(a) : "l"(p));
    return a;
}
__device__ __forceinline__ void cp16(uint32_t dst, const void* src) {
    asm volatile("cp.async.cg.shared.global [%0], [%1], 16;" :: "r"(dst), "l"(src) : "memory");
}
__device__ __forceinline__ void ldx4(uint32_t r[4], uint32_t addr) {
    asm volatile("ldmatrix.sync.aligned.m8n8.x4.shared.b16 {%0,%1,%2,%3}, [%4];"
                 : "=r"(r[0]), "=r"(r[1]), "=r"(r[2]), "=r"(r[3]) : "r"(addr));
}
__device__ __forceinline__ void mma_bf16(float c[4], const uint32_t a[4], uint32_t b0, uint32_t b1) {
    asm volatile("mma.sync.aligned.m16n8k16.row.col.f32.bf16.bf16.f32 "
                 "{%0,%1,%2,%3}, {%4,%5,%6,%7}, {%8,%9}, {%0,%1,%2,%3};"
                 : "+f"(c[0]), "+f"(c[1]), "+f"(c[2]), "+f"(c[3])
                 : "r"(a[0]), "r"(a[1]), "r"(a[2]), "r"(a[3]), "r"(b0), "r"(b1));
}
__device__ __forceinline__ void split4(float4 v, uint2& hiw, uint2& low) {
    uint32_t ux = __float_as_uint(v.x), uy = __float_as_uint(v.y);
    uint32_t uz = __float_as_uint(v.z), uw = __float_as_uint(v.w);
    hiw.x = __byte_perm(ux, uy, 0x7632);
    hiw.y = __byte_perm(uz, uw, 0x7632);
    float rx = v.x - __uint_as_float(ux & 0xFFFF0000u);
    float ry = v.y - __uint_as_float(uy & 0xFFFF0000u);
    float rz = v.z - __uint_as_float(uz & 0xFFFF0000u);
    float rw = v.w - __uint_as_float(uw & 0xFFFF0000u);
    __nv_bfloat162 l01 = __floats2bfloat162_rn(rx, ry);
    __nv_bfloat162 l23 = __floats2bfloat162_rn(rz, rw);
    low.x = *(uint32_t*)&l01;
    low.y = *(uint32_t*)&l23;
}

// ================================================================ bf16 MMA GEMM
// C[nrows,Nout] = (Ahi+Alo)[.,K] @ (Whi+Wlo)[Nout,K]^T (+bias)
// grid: (Nout/128 fastest, rowblocks) for A-reuse in L2.
// 2-stage cp.async, BK=32, 256 threads, 2 CTA/SM.
// MMA issue is term-major within each p-block: same-acc chain distance = 4.
__global__ __launch_bounds__(256, 2)
void k_gemm_mma(const __nv_bfloat16* __restrict__ Ahi, const __nv_bfloat16* __restrict__ Alo,
                int K,
                const __nv_bfloat16* __restrict__ Whi, const __nv_bfloat16* __restrict__ Wlo,
                float* __restrict__ C, int Nout, const float* __restrict__ bias, int nrows) {
    extern __shared__ char smem[];
    const uint32_t sb = smem_u32(smem);
    const int MTX = 10240;           // 128 rows * 80 B
    const int STAGE = 4 * MTX;       // 40 KB

    const int tid = threadIdx.x, wid = tid >> 5, lane = tid & 31;
    const int wm = wid & 3, wn = wid >> 2;
    const int bcol = blockIdx.x * 128, brow = blockIdx.y * 128;   // x = column (fast)
    const int nit = K >> 5;

    const int c0 = tid * 2, c1 = tid * 2 + 1;
    const int r0 = c0 >> 2, k16_0 = c0 & 3;
    const int r1 = c1 >> 2, k16_1 = c1 & 3;

    const int g = lane >> 3, lr = lane & 7;
    const uint32_t a_row = (uint32_t)(wm * 32 + (g & 1) * 8 + lr);
    const uint32_t b_row = (uint32_t)(wn * 64 + (g & 1) * 8 + lr);
    const uint32_t kg = (uint32_t)((g >> 1) * 16);

    float acc[2][8][4];
#pragma unroll
    for (int m = 0; m < 2; m++)
#pragma unroll
        for (int n = 0; n < 8; n++)
#pragma unroll
            for (int v = 0; v < 4; v++) acc[m][n][v] = 0.f;

#define LOAD_STAGE(I) do {                                                            \
    uint32_t _d = sb + ((I) & 1) * STAGE; int _k0 = (I) * 32;                         \
    cp16(_d + r0 * 80 + k16_0 * 16,           Ahi + (size_t)(brow + r0) * K + _k0 + k16_0 * 8); \
    cp16(_d + r1 * 80 + k16_1 * 16,           Ahi + (size_t)(brow + r1) * K + _k0 + k16_1 * 8); \
    cp16(_d + MTX + r0 * 80 + k16_0 * 16,     Alo + (size_t)(brow + r0) * K + _k0 + k16_0 * 8); \
    cp16(_d + MTX + r1 * 80 + k16_1 * 16,     Alo + (size_t)(brow + r1) * K + _k0 + k16_1 * 8); \
    cp16(_d + 2 * MTX + r0 * 80 + k16_0 * 16, Whi + (size_t)(bcol + r0) * K + _k0 + k16_0 * 8); \
    cp16(_d + 2 * MTX + r1 * 80 + k16_1 * 16, Whi + (size_t)(bcol + r1) * K + _k0 + k16_1 * 8); \
    cp16(_d + 3 * MTX + r0 * 80 + k16_0 * 16, Wlo + (size_t)(bcol + r0) * K + _k0 + k16_0 * 8); \
    cp16(_d + 3 * MTX + r1 * 80 + k16_1 * 16, Wlo + (size_t)(bcol + r1) * K + _k0 + k16_1 * 8); \
    asm volatile("cp.async.commit_group;" ::: "memory");                              \
} while (0)

    LOAD_STAGE(0);

    for (int i = 0; i < nit; i++) {
        if (i + 1 < nit) {
            LOAD_STAGE(i + 1);
            asm volatile("cp.async.wait_group 1;" ::: "memory");
        } else {
            asm volatile("cp.async.wait_group 0;" ::: "memory");
        }
        __syncthreads();

        const uint32_t base = sb + (i & 1) * STAGE;
#pragma unroll
        for (int kst = 0; kst < 2; kst++) {
            const uint32_t acol = kg + kst * 32;
            uint32_t ah[2][4], al[2][4];
#pragma unroll
            for (int m = 0; m < 2; m++) {
                uint32_t aa = base + (a_row + m * 16) * 80 + acol;
                ldx4(ah[m], aa);
                ldx4(al[m], aa + MTX);
            }
#pragma unroll
            for (int p = 0; p < 4; p++) {
                uint32_t bh[4], bl[4];
                uint32_t ba = base + 2 * MTX + (b_row + p * 16) * 80 + acol;
                ldx4(bh, ba);
                ldx4(bl, ba + MTX);
                // term-major: 4 independent accumulators between same-acc reuse
#pragma unroll
                for (int m = 0; m < 2; m++)
#pragma unroll
                    for (int s = 0; s < 2; s++)
                        mma_bf16(acc[m][p * 2 + s], ah[m], bh[s], bh[s + 2]);
#pragma unroll
                for (int m = 0; m < 2; m++)
#pragma unroll
                    for (int s = 0; s < 2; s++)
                        mma_bf16(acc[m][p * 2 + s], ah[m], bl[s], bl[s + 2]);
#pragma unroll
                for (int m = 0; m < 2; m++)
#pragma unroll
                    for (int s = 0; s < 2; s++)
                        mma_bf16(acc[m][p * 2 + s], al[m], bh[s], bh[s + 2]);
            }
        }
        __syncthreads();
    }
#undef LOAD_STAGE

    const int q = lane >> 2, qt = lane & 3;
#pragma unroll
    for (int m = 0; m < 2; m++) {
        int row = brow + wm * 32 + m * 16 + q;
#pragma unroll
        for (int n = 0; n < 8; n++) {
            int colb = bcol + wn * 64 + n * 8 + qt * 2;
            float* cc = acc[m][n];
            float bx = 0.f, by = 0.f;
            if (bias) { bx = bias[colb]; by = bias[colb + 1]; }
            if (row < nrows)
                *(float2*)(C + (size_t)row * Nout + colb) = make_float2(cc[0] + bx, cc[1] + by);
            if (row + 8 < nrows)
                *(float2*)(C + (size_t)(row + 8) * Nout + colb) = make_float2(cc[2] + bx, cc[3] + by);
        }
    }
}

// ================================================================ CSR pull aggregation
__global__ __launch_bounds__(256)
void k_agg_csr(const int* __restrict__ rowptr, const int* __restrict__ csrcol,
               const float* __restrict__ dinv, const float* __restrict__ hp,
               const float* __restrict__ bias,
               __nv_bfloat16* __restrict__ hi, __nv_bfloat16* __restrict__ lo, int col_base) {
    int gw = (int)((blockIdx.x * blockDim.x + threadIdx.x) >> 5);
    int lane = threadIdx.x & 31;
    if (gw >= N_NODES) return;
    int s = __ldg(rowptr + gw), e = __ldg(rowptr + gw + 1);
    const int cb4 = col_base >> 2;

    float dself = __ldg(dinv + gw);
    const float4* self = (const float4*)(hp + (size_t)gw * D_HID) + cb4;
    float4 acc[2];
#pragma unroll
    for (int i = 0; i < 2; i++) {
        float4 v = __ldg(self + lane + i * 32);
        acc[i] = make_float4(dself * v.x, dself * v.y, dself * v.z, dself * v.w);
    }

    int j = s;
    for (; j + 1 < e; j += 2) {
        int c0 = __ldg(csrcol + j), c1 = __ldg(csrcol + j + 1);
        float w0 = __ldg(dinv + c0), w1 = __ldg(dinv + c1);
        const float4* s0 = (const float4*)(hp + (size_t)c0 * D_HID) + cb4;
        const float4* s1 = (const float4*)(hp + (size_t)c1 * D_HID) + cb4;
#pragma unroll
        for (int i = 0; i < 2; i++) {
            float4 v0 = __ldg(s0 + lane + i * 32);
            float4 v1 = __ldg(s1 + lane + i * 32);
            acc[i].x = fmaf(w0, v0.x, fmaf(w1, v1.x, acc[i].x));
            acc[i].y = fmaf(w0, v0.y, fmaf(w1, v1.y, acc[i].y));
            acc[i].z = fmaf(w0, v0.z, fmaf(w1, v1.z, acc[i].z));
            acc[i].w = fmaf(w0, v0.w, fmaf(w1, v1.w, acc[i].w));
        }
    }
    if (j < e) {
        int c = __ldg(csrcol + j);
        float w = __ldg(dinv + c);
        const float4* sv = (const float4*)(hp + (size_t)c * D_HID) + cb4;
#pragma unroll
        for (int i = 0; i < 2; i++) {
            float4 v = __ldg(sv + lane + i * 32);
            acc[i].x = fmaf(w, v.x, acc[i].x);
            acc[i].y = fmaf(w, v.y, acc[i].y);
            acc[i].z = fmaf(w, v.z, acc[i].z);
            acc[i].w = fmaf(w, v.w, acc[i].w);
        }
    }

    size_t obase = (size_t)gw * D_HID;
#pragma unroll
    for (int i = 0; i < 2; i++) {
        int f4 = cb4 + lane + i * 32;
        float4 b = __ldg((const float4*)bias + f4);
        float4 v;
        v.x = fmaxf(fmaf(dself, acc[i].x, b.x), 0.f);
        v.y = fmaxf(fmaf(dself, acc[i].y, b.y), 0.f);
        v.z = fmaxf(fmaf(dself, acc[i].z, b.z), 0.f);
        v.w = fmaxf(fmaf(dself, acc[i].w, b.w), 0.f);
        uint2 hw, lw;
        split4(v, hw, lw);
        *(uint2*)(hi + obase + (size_t)f4 * 4) = hw;
        *(uint2*)(lo + obase + (size_t)f4 * 4) = lw;
    }
}

// ================================================================ prep kernels
__global__ void k_prep_all(const float* __restrict__ W1, const float* __restrict__ W2,
                           const float* __restrict__ W3, const float* __restrict__ Wfc,
                           __nv_bfloat16* __restrict__ whi, __nv_bfloat16* __restrict__ wlo,
                           int* __restrict__ ideg) {
    int idx = blockIdx.x * blockDim.x + threadIdx.x;
    if (idx == 0) g_is32 = 0;
    if (idx < N_NODES) ideg[idx] = 0;
    if (idx >= W_TOTAL) return;
    const float* W; int K, Nout, base;
    if (idx < W_OFF_L2)      { W = W1;  K = 256; Nout = 512; base = W_OFF_L1; }
    else if (idx < W_OFF_L3) { W = W2;  K = 512; Nout = 512; base = W_OFF_L2; }
    else if (idx < W_OFF_FC) { W = W3;  K = 512; Nout = 512; base = W_OFF_L3; }
    else                     { W = Wfc; K = 512; Nout = 256; base = W_OFF_FC; }
    int local = idx - base;
    int k = local / Nout, n = local - k * Nout;
    float v = W[local];
    uint32_t u = __float_as_uint(v);
    float h = __uint_as_float(u & 0xFFFF0000u);
    ushort hs = (ushort)(u >> 16);
    whi[base + (size_t)n * K + k] = *reinterpret_cast<__nv_bfloat16*>(&hs);
    wlo[base + (size_t)n * K + k] = __float2bfloat16_rn(v - h);
}

__global__ void k_detect(const long long* __restrict__ p, int n) {
    int i = blockIdx.x * blockDim.x + threadIdx.x;
    if (i < n) {
        long long v = p[i];
        if (v < 0 || v >= N_NODES) atomicOr(&g_is32, 1);
    }
}
__global__ void k_split(const float4* __restrict__ A,
                        __nv_bfloat16* __restrict__ hi, __nv_bfloat16* __restrict__ lo, int total4) {
    int i = blockIdx.x * blockDim.x + threadIdx.x;
    if (i >= total4) return;
    uint2 hw, lw;
    split4(A[i], hw, lw);
    *(uint2*)(hi + (size_t)i * 4) = hw;
    *(uint2*)(lo + (size_t)i * 4) = lw;
}
__global__ void k_convert_count(const void* __restrict__ ei, int E,
                                int* __restrict__ row, int* __restrict__ col,
                                int* __restrict__ ideg) {
    int i = blockIdx.x * blockDim.x + threadIdx.x;
    if (i >= E) return;
    int r, c;
    if (g_is32) {
        const int* p = (const int*)ei;
        r = p[i]; c = p[E + i];
    } else {
        const long long* p = (const long long*)ei;
        r = (int)p[i]; c = (int)p[E + i];
    }
    row[i] = r; col[i] = c;
    atomicAdd(&ideg[r], 1);
}
__global__ __launch_bounds__(1024)
void k_scan(const int* __restrict__ deg, int* __restrict__ rowptr,
            int* __restrict__ cursor, float* __restrict__ dinv, int n) {
    __shared__ int warpsum[32];
    __shared__ int carry, total;
    int tid = threadIdx.x, w = tid >> 5, lane = tid & 31;
    if (tid == 0) carry = 0;
    __syncthreads();
    for (int base = 0; base < n; base += 1024) {
        int idx = base + tid;
        int v = (idx < n) ? deg[idx] : 0;
        if (idx < n) dinv[idx] = rsqrtf((float)(v + 1));
        int x = v;
#pragma unroll
        for (int o = 1; o < 32; o <<= 1) {
            int y = __shfl_up_sync(0xFFFFFFFFu, x, o);
            if (lane >= o) x += y;
        }
        if (lane == 31) warpsum[w] = x;
        __syncthreads();
        if (tid == 0) {
            int s = 0;
            for (int i = 0; i < 32; i++) { int t = warpsum[i]; warpsum[i] = s; s += t; }
            total = s;
        }
        __syncthreads();
        int excl = carry + warpsum[w] + x - v;
        if (idx < n) { rowptr[idx] = excl; cursor[idx] = excl; }
        __syncthreads();
        if (tid == 0) carry += total;
        __syncthreads();
    }
    if (threadIdx.x == 0) rowptr[n] = carry;
}
__global__ void k_csr_scatter(const int* __restrict__ row, const int* __restrict__ col,
                              int* __restrict__ cursor, int* __restrict__ csrcol, int E) {
    int i = blockIdx.x * blockDim.x + threadIdx.x;
    if (i >= E) return;
    int p = atomicAdd(&cursor[row[i]], 1);
    csrcol[p] = col[i];
}

// ================================================================ launch
extern "C" void kernel_launch(void* const* d_in, const int* in_sizes, int n_in,
                              void* d_out, int out_size) {
    const float* x   = (const float*)d_in[0];
    const void*  ei  = d_in[1];
    const float* W1  = (const float*)d_in[2];
    const float* b1  = (const float*)d_in[3];
    const float* W2  = (const float*)d_in[4];
    const float* b2  = (const float*)d_in[5];
    const float* W3  = (const float*)d_in[6];
    const float* b3  = (const float*)d_in[7];
    const float* Wfc = (const float*)d_in[8];
    const float* bfc = (const float*)d_in[9];
    int E = in_sizes[1] / 2;
    if (E > E_MAX) E = E_MAX;

    float *dinv, *hp;
    int *row, *col, *ideg, *rowptr, *cursor, *csrcol;
    __nv_bfloat16 *ahi, *alo, *whi, *wlo;
    cudaGetSymbolAddress((void**)&dinv,   g_dinv);
    cudaGetSymbolAddress((void**)&hp,     g_hp);
    cudaGetSymbolAddress((void**)&row,    g_row);
    cudaGetSymbolAddress((void**)&col,    g_col);
    cudaGetSymbolAddress((void**)&ideg,   g_ideg);
    cudaGetSymbolAddress((void**)&rowptr, g_rowptr);
    cudaGetSymbolAddress((void**)&cursor, g_cursor);
    cudaGetSymbolAddress((void**)&csrcol, g_csrcol);
    cudaGetSymbolAddress((void**)&ahi,    g_ahi);
    cudaGetSymbolAddress((void**)&alo,    g_alo);
    cudaGetSymbolAddress((void**)&whi,    g_whi);
    cudaGetSymbolAddress((void**)&wlo,    g_wlo);

    const int SMEM_GEMM = 2 * 4 * 10240;  // 80 KB
    cudaFuncSetAttribute(k_gemm_mma, cudaFuncAttributeMaxDynamicSharedMemorySize, SMEM_GEMM);

    const int T = 256;
    int gE = (E + T - 1) / T;
    int s1 = N_NODES * 256 / 4;

    dim3 gridH(4, (N_NODES + 127) / 128);   // x = column block (fast) for A L2 reuse
    dim3 gridO(2, (N_NODES + 127) / 128);
    int gAgg = (int)(((long long)N_NODES * 32 + T - 1) / T);

    // 1. weights + zero ideg/flag
    k_prep_all<<<(W_TOTAL + T - 1) / T, T>>>(W1, W2, W3, Wfc, whi, wlo, ideg);
    // 2. dtype detect
    k_detect<<<gE, T>>>((const long long*)ei, E);
    // 3. split x
    k_split<<<(s1 + T - 1) / T, T>>>((const float4*)x, ahi, alo, s1);
    // 4. layer-1 GEMM (profiled launch)
    k_gemm_mma<<<gridH, 256, SMEM_GEMM>>>(ahi, alo, 256, whi + W_OFF_L1, wlo + W_OFF_L1,
                                          hp, 512, nullptr, N_NODES);
    // 5-7. graph prep
    k_convert_count<<<gE, T>>>(ei, E, row, col, ideg);
    k_scan<<<1, 1024>>>(ideg, rowptr, cursor, dinv, N_NODES);
    k_csr_scatter<<<gE, T>>>(row, col, cursor, csrcol, E);

    // layer 1 agg
    k_agg_csr<<<gAgg, T>>>(rowptr, csrcol, dinv, hp, b1, ahi, alo, 0);
    k_agg_csr<<<gAgg, T>>>(rowptr, csrcol, dinv, hp, b1, ahi, alo, 256);

    // layer 2
    k_gemm_mma<<<gridH, 256, SMEM_GEMM>>>(ahi, alo, 512, whi + W_OFF_L2, wlo + W_OFF_L2,
                                          hp, 512, nullptr, N_NODES);
    k_agg_csr<<<gAgg, T>>>(rowptr, csrcol, dinv, hp, b2, ahi, alo, 0);
    k_agg_csr<<<gAgg, T>>>(rowptr, csrcol, dinv, hp, b2, ahi, alo, 256);

    // layer 3
    k_gemm_mma<<<gridH, 256, SMEM_GEMM>>>(ahi, alo, 512, whi + W_OFF_L3, wlo + W_OFF_L3,
                                          hp, 512, nullptr, N_NODES);
    k_agg_csr<<<gAgg, T>>>(rowptr, csrcol, dinv, hp, b3, ahi, alo, 0);
    k_agg_csr<<<gAgg, T>>>(rowptr, csrcol, dinv, hp, b3, ahi, alo, 256);

    // final FC
    k_gemm_mma<<<gridO, 256, SMEM_GEMM>>>(ahi, alo, 512, whi + W_OFF_FC, wlo + W_OFF_FC,
                                          (float*)d_out, 256, bfc, N_NODES);
}